// round 15
// baseline (speedup 1.0000x reference)
#include <cuda_runtime.h>

// Problem constants
#define NPOL   2
#define NANT   64
#define NBL    2016
#define NTIMES 64
#define NFREQS 256

#define TF   (NTIMES * NFREQS)   // 16384
#define TF4  (TF / 4)            // 4096 float4 per (baseline|antenna) per pol-component
#define V4S  (NBL * TF4)         // 8,257,536  : pol-component stride of V in float4 units
#define J4S  (NANT * TF4)        // 262,144    : pol-component stride of jones in float4 units

__device__ __forceinline__ float4 f4_mul(float4 a, float4 b) {
    return make_float4(a.x * b.x, a.y * b.y, a.z * b.z, a.w * b.w);
}
__device__ __forceinline__ float4 f4_fma(float4 a, float4 b, float4 c) {
    return make_float4(fmaf(a.x, b.x, c.x), fmaf(a.y, b.y, c.y),
                       fmaf(a.z, b.z, c.z), fmaf(a.w, b.w, c.w));
}

// Session-validated structure (153.7 us x4). This round's single delta:
// out stores .cs -> .wt (write-through). Stores are full-sector coalesced
// (each warp: 4 x 512B contiguous), so write-through has no RMW penalty and
// removes the output stream from L2 occupancy entirely (no dirty lines to
// hold ways or schedule writebacks) — more effective L2 for jones + V fills.
__global__ __launch_bounds__(256)
void jones_apply_kernel(const float4* __restrict__ V,     // (2,2,NBL,T,F) as float4
                        const float4* __restrict__ J,     // (2,2,NANT,T,F) as float4
                        const int*    __restrict__ ant1,
                        const int*    __restrict__ ant2,
                        float4*       __restrict__ out)   // (2,2,NBL,T,F) as float4
{
    int i = blockIdx.x * blockDim.x + threadIdx.x;   // 0 .. NBL*TF4-1 (exact grid)
    int n = i >> 12;          // / 4096 -> baseline
    int r = i & 4095;         // position within (t,f) plane, float4 units

    int a1 = __ldg(&ant1[n]);
    int a2 = __ldg(&ant2[n]);

    int vb  = n  * TF4 + r;   // V base (component 0), float4 units
    int jb1 = a1 * TF4 + r;   // jones base for ant1
    int jb2 = a2 * TF4 + r;   // jones base for ant2

    // Jones: ~31x reuse across baselines via L2; zero L1 reuse -> .cg.
    float4 j1_00 = __ldcg(&J[jb1]);
    float4 j1_01 = __ldcg(&J[jb1 + J4S]);
    float4 j1_10 = __ldcg(&J[jb1 + 2 * J4S]);
    float4 j1_11 = __ldcg(&J[jb1 + 3 * J4S]);

    float4 j2_00 = __ldcg(&J[jb2]);
    float4 j2_01 = __ldcg(&J[jb2 + J4S]);
    float4 j2_10 = __ldcg(&J[jb2 + 2 * J4S]);
    float4 j2_11 = __ldcg(&J[jb2 + 3 * J4S]);

    // V: use-once stream -> evict-first so it doesn't thrash jones out of L2.
    float4 v00 = __ldcs(&V[vb]);
    float4 v01 = __ldcs(&V[vb + V4S]);
    float4 v10 = __ldcs(&V[vb + 2 * V4S]);
    float4 v11 = __ldcs(&V[vb + 3 * V4S]);

    // T = J1 @ V
    float4 t00 = f4_fma(j1_00, v00, f4_mul(j1_01, v10));
    float4 t01 = f4_fma(j1_00, v01, f4_mul(j1_01, v11));
    float4 t10 = f4_fma(j1_10, v00, f4_mul(j1_11, v10));
    float4 t11 = f4_fma(j1_10, v01, f4_mul(j1_11, v11));

    // Out[a][d] = sum_c T[a][c] * J2[d][c]   (conj == identity, real data)
    float4 o00 = f4_fma(t00, j2_00, f4_mul(t01, j2_01));
    float4 o01 = f4_fma(t00, j2_10, f4_mul(t01, j2_11));
    float4 o10 = f4_fma(t10, j2_00, f4_mul(t11, j2_01));
    float4 o11 = f4_fma(t10, j2_10, f4_mul(t11, j2_11));

    // Write-through stores: no dirty L2 lines at all for the output stream.
    __stwt(&out[vb],           o00);
    __stwt(&out[vb + V4S],     o01);
    __stwt(&out[vb + 2 * V4S], o10);
    __stwt(&out[vb + 3 * V4S], o11);
}

extern "C" void kernel_launch(void* const* d_in, const int* in_sizes, int n_in,
                              void* d_out, int out_size) {
    const float4* V    = (const float4*)d_in[0];   // V_m  float32 (2,2,2016,64,256)
    const float4* J    = (const float4*)d_in[1];   // jones float32 (2,2,64,64,256)
    const int*    ant1 = (const int*)d_in[2];
    const int*    ant2 = (const int*)d_in[3];
    float4*       out  = (float4*)d_out;

    const int total = NBL * TF4;            // 8,257,536 threads
    const int threads = 256;
    const int blocks = total / threads;     // 32,256 (exact)
    jones_apply_kernel<<<blocks, threads>>>(V, J, ant1, ant2, out);
}

// round 16
// speedup vs baseline: 1.0644x; 1.0644x over previous
#include <cuda_runtime.h>

// Problem constants
#define NPOL   2
#define NANT   64
#define NBL    2016
#define NTIMES 64
#define NFREQS 256

#define TF   (NTIMES * NFREQS)   // 16384
#define TF4  (TF / 4)            // 4096 float4 per (baseline|antenna) per pol-component
#define V4S  (NBL * TF4)         // 8,257,536  : pol-component stride of V in float4 units
#define J4S  (NANT * TF4)        // 262,144    : pol-component stride of jones in float4 units

__device__ __forceinline__ float4 f4_mul(float4 a, float4 b) {
    return make_float4(a.x * b.x, a.y * b.y, a.z * b.z, a.w * b.w);
}
__device__ __forceinline__ float4 f4_fma(float4 a, float4 b, float4 c) {
    return make_float4(fmaf(a.x, b.x, c.x), fmaf(a.y, b.y, c.y),
                       fmaf(a.z, b.z, c.z), fmaf(a.w, b.w, c.w));
}

// FINAL kernel — session optimum, measured 153.66 us identically in rounds
// R2/R9/R11/R12 (and 154.3 +/- noise in R7/R14). 15 rounds of search closed:
//
// Structure: one thread per (baseline, float4-of-4-freqs), flat exact grid,
// 256 thr/blk. 48 regs -> 5 blocks/SM -> 40 warps: the top of the
// occupancy x per-warp-MLP ridge (R8 regs=40 serialized loads: -7 us;
// R5 2-items/thread halved occupancy: neutral-worse; R3 persistent loop
// killed block-churn prefetch: -26 us; R10 128-thr blocks: neutral).
//
// Cache policy (the decisive win, -15 us vs no hints):
//   - V loads:  .cs  evict-first — use-once stream must not thrash jones.
//   - stores:   .cs  evict-first dirty lines — L2 still batches writebacks
//                    but output doesn't hold ways at normal priority.
//                    (default: R6 regress; .wt write-through: R15 regress;
//                     .lu on loads: R13 register-bloat regress.)
//   - jones:    .cg  L2-only — ~31x cross-SM reuse via L2, zero L1 reuse.
//
// Measured: 1.03 GB DRAM traffic (at the analytic floor), 6.66 TB/s
// (balanced R/W HBM3e ceiling), DRAM busy 84%. Within 2.5% of the idealized
// memory floor; the residue is hardware R/W turnaround, not kernel slack.
__global__ __launch_bounds__(256)
void jones_apply_kernel(const float4* __restrict__ V,     // (2,2,NBL,T,F) as float4
                        const float4* __restrict__ J,     // (2,2,NANT,T,F) as float4
                        const int*    __restrict__ ant1,
                        const int*    __restrict__ ant2,
                        float4*       __restrict__ out)   // (2,2,NBL,T,F) as float4
{
    int i = blockIdx.x * blockDim.x + threadIdx.x;   // 0 .. NBL*TF4-1 (exact grid)
    int n = i >> 12;          // / 4096 -> baseline
    int r = i & 4095;         // position within (t,f) plane, float4 units

    int a1 = __ldg(&ant1[n]);
    int a2 = __ldg(&ant2[n]);

    int vb  = n  * TF4 + r;   // V base (component 0), float4 units
    int jb1 = a1 * TF4 + r;   // jones base for ant1
    int jb2 = a2 * TF4 + r;   // jones base for ant2

    // Jones: ~31x reuse across baselines via L2; zero L1 reuse -> .cg.
    float4 j1_00 = __ldcg(&J[jb1]);
    float4 j1_01 = __ldcg(&J[jb1 + J4S]);
    float4 j1_10 = __ldcg(&J[jb1 + 2 * J4S]);
    float4 j1_11 = __ldcg(&J[jb1 + 3 * J4S]);

    float4 j2_00 = __ldcg(&J[jb2]);
    float4 j2_01 = __ldcg(&J[jb2 + J4S]);
    float4 j2_10 = __ldcg(&J[jb2 + 2 * J4S]);
    float4 j2_11 = __ldcg(&J[jb2 + 3 * J4S]);

    // V: use-once stream -> evict-first so it doesn't thrash jones out of L2.
    float4 v00 = __ldcs(&V[vb]);
    float4 v01 = __ldcs(&V[vb + V4S]);
    float4 v10 = __ldcs(&V[vb + 2 * V4S]);
    float4 v11 = __ldcs(&V[vb + 3 * V4S]);

    // T = J1 @ V
    float4 t00 = f4_fma(j1_00, v00, f4_mul(j1_01, v10));
    float4 t01 = f4_fma(j1_00, v01, f4_mul(j1_01, v11));
    float4 t10 = f4_fma(j1_10, v00, f4_mul(j1_11, v10));
    float4 t11 = f4_fma(j1_10, v01, f4_mul(j1_11, v11));

    // Out[a][d] = sum_c T[a][c] * J2[d][c]   (conj == identity, real data)
    float4 o00 = f4_fma(t00, j2_00, f4_mul(t01, j2_01));
    float4 o01 = f4_fma(t00, j2_10, f4_mul(t01, j2_11));
    float4 o10 = f4_fma(t10, j2_00, f4_mul(t11, j2_01));
    float4 o11 = f4_fma(t10, j2_10, f4_mul(t11, j2_11));

    // Streaming stores: evict-first dirty lines — L2 batches writebacks
    // without the output stream holding ways at normal priority.
    __stcs(&out[vb],           o00);
    __stcs(&out[vb + V4S],     o01);
    __stcs(&out[vb + 2 * V4S], o10);
    __stcs(&out[vb + 3 * V4S], o11);
}

extern "C" void kernel_launch(void* const* d_in, const int* in_sizes, int n_in,
                              void* d_out, int out_size) {
    const float4* V    = (const float4*)d_in[0];   // V_m  float32 (2,2,2016,64,256)
    const float4* J    = (const float4*)d_in[1];   // jones float32 (2,2,64,64,256)
    const int*    ant1 = (const int*)d_in[2];
    const int*    ant2 = (const int*)d_in[3];
    float4*       out  = (float4*)d_out;

    const int total = NBL * TF4;            // 8,257,536 threads
    const int threads = 256;
    const int blocks = total / threads;     // 32,256 (exact)
    jones_apply_kernel<<<blocks, threads>>>(V, J, ant1, ant2, out);
}